// round 8
// baseline (speedup 1.0000x reference)
#include <cuda_runtime.h>

#define N_NODES 100000
#define N_EDGES 3200000
#define D_IN    128
#define D_HID   16
#define N_CLS   2

#define NB_SCAN 400          // 400 * 256 = 102400 >= N_NODES

// ---- scratch (static device memory; no runtime allocation) ----
__device__ __align__(128) int   g_cnt [NB_SCAN * 256];   // in-degree (excl self)
__device__ __align__(128) int   g_ptr [N_NODES];         // CSR row start (exclusive scan)
__device__ __align__(128) int   g_fill[N_NODES];         // fill cursor
__device__ __align__(128) int   g_bsum[512];             // block sums for scan
__device__ __align__(128) float g_dinv[N_NODES];
__device__ __align__(128) int   g_csr_src[N_EDGES];      // src ids grouped by dst
__device__ __align__(128) float g_g1  [N_NODES * D_HID]; // layer-1 messages (h1*dinv)
__device__ __align__(128) float g_g2  [N_NODES * N_CLS]; // layer-2 messages (h2*dinv)

// ---- 1) zero histogram ----
__global__ void k_zero() {
    int i = blockIdx.x * blockDim.x + threadIdx.x;
    if (i < NB_SCAN * 256) g_cnt[i] = 0;
}

// ---- 2) in-degree histogram ----
__global__ void k_cnt(const int* __restrict__ ei_dst) {
    int e = blockIdx.x * blockDim.x + threadIdx.x;
    if (e < N_EDGES) atomicAdd(&g_cnt[ei_dst[e]], 1);
}

// ---- 3a) per-block sums ----
__global__ __launch_bounds__(256) void k_scan1() {
    __shared__ int s[256];
    int t = threadIdx.x;
    s[t] = g_cnt[blockIdx.x * 256 + t];
    __syncthreads();
    for (int off = 128; off > 0; off >>= 1) {
        if (t < off) s[t] += s[t + off];
        __syncthreads();
    }
    if (t == 0) g_bsum[blockIdx.x] = s[0];
}

// ---- 3b) scan block sums (single block, warp-shuffle scan) ----
__global__ __launch_bounds__(512) void k_scan2() {
    __shared__ int wsum[16];
    int t = threadIdx.x;
    int lane = t & 31, w = t >> 5;
    int v = (t < NB_SCAN) ? g_bsum[t] : 0;
    int x = v;
#pragma unroll
    for (int off = 1; off < 32; off <<= 1) {
        int y = __shfl_up_sync(0xffffffffu, x, off);
        if (lane >= off) x += y;
    }
    if (lane == 31) wsum[w] = x;
    __syncthreads();
    if (w == 0) {
        int s = (lane < 16) ? wsum[lane] : 0;
#pragma unroll
        for (int off = 1; off < 16; off <<= 1) {
            int y = __shfl_up_sync(0xffffffffu, s, off);
            if (lane >= off) s += y;
        }
        if (lane < 16) wsum[lane] = s;
    }
    __syncthreads();
    int excl = x - v + (w > 0 ? wsum[w - 1] : 0);
    if (t < NB_SCAN) g_bsum[t] = excl;
}

// ---- 3c) per-block exclusive scan + offsets; also dinv, fill init ----
__global__ __launch_bounds__(256) void k_scan3() {
    __shared__ int s[256];
    int t = threadIdx.x;
    int i = blockIdx.x * 256 + t;
    int v = g_cnt[i];
    s[t] = v;
    __syncthreads();
    for (int off = 1; off < 256; off <<= 1) {
        int a = (t >= off) ? s[t - off] : 0;
        __syncthreads();
        s[t] += a;
        __syncthreads();
    }
    int excl = s[t] - v + g_bsum[blockIdx.x];
    if (i < N_NODES) {
        g_ptr[i]  = excl;
        g_fill[i] = excl;
        g_dinv[i] = rsqrtf((float)(v + 1));   // +1 self-loop
    }
}

// ---- 4) fill CSR: src ids grouped by dst ----
__global__ void k_fill(const int* __restrict__ ei_src,
                       const int* __restrict__ ei_dst) {
    int e = blockIdx.x * blockDim.x + threadIdx.x;
    if (e >= N_EDGES) return;
    int pos = atomicAdd(&g_fill[ei_dst[e]], 1);
    g_csr_src[pos] = ei_src[e];
}

// ---- 5) g1 = (x @ W1) * dinv ----
__global__ __launch_bounds__(256) void k_gemm1(const float* __restrict__ x,
                                               const float* __restrict__ W1) {
    __shared__ float Ws[D_IN * D_HID];
    __shared__ float Xs[16][D_IN + 1];
    int tid = threadIdx.x;
    int nodeBase = blockIdx.x * 16;

    for (int i = tid; i < D_IN * D_HID; i += 256) Ws[i] = W1[i];
    for (int i = tid; i < 16 * D_IN; i += 256) {
        int r = i >> 7, c = i & 127;
        Xs[r][c] = x[(nodeBase + r) * D_IN + c];
    }
    __syncthreads();

    int node = tid >> 4, col = tid & 15;
    float acc = 0.f;
#pragma unroll
    for (int k = 0; k < D_IN; k++) acc += Xs[node][k] * Ws[k * D_HID + col];

    int gn = nodeBase + node;
    g_g1[gn * D_HID + col] = acc * g_dinv[gn];
}

// ---- 6) layer-1 gather + fused layer-2 node GEMM ----
// warp per node; 4 lanes per edge (one coalesced 64B row), 8 edges/iter,
// unrolled x2 -> 16 independent edge-row loads in flight per warp.
__global__ __launch_bounds__(256) void k_gather1(const float* __restrict__ b1,
                                                 const float* __restrict__ W2) {
    int n    = (blockIdx.x * blockDim.x + threadIdx.x) >> 5;   // node id
    int lane = threadIdx.x & 31;
    int g    = lane >> 2;        // edge group 0..7
    int q    = lane & 3;         // quad: dims q*4 .. q*4+3

    int ptr = g_ptr[n];
    int deg = g_cnt[n];

    float4 acc = make_float4(0.f, 0.f, 0.f, 0.f);
    if (g == 0)                                              // self-loop
        acc = *reinterpret_cast<const float4*>(&g_g1[n * D_HID + q * 4]);

    int i = g;
    for (; i + 8 < deg; i += 16) {
        int s0 = g_csr_src[ptr + i];
        int s1 = g_csr_src[ptr + i + 8];
        float4 r0 = *reinterpret_cast<const float4*>(&g_g1[s0 * D_HID + q * 4]);
        float4 r1 = *reinterpret_cast<const float4*>(&g_g1[s1 * D_HID + q * 4]);
        acc.x += r0.x + r1.x; acc.y += r0.y + r1.y;
        acc.z += r0.z + r1.z; acc.w += r0.w + r1.w;
    }
    if (i < deg) {
        int s = g_csr_src[ptr + i];
        float4 r = *reinterpret_cast<const float4*>(&g_g1[s * D_HID + q * 4]);
        acc.x += r.x; acc.y += r.y; acc.z += r.z; acc.w += r.w;
    }

#pragma unroll
    for (int off = 16; off >= 4; off >>= 1) {                // reduce edge groups
        acc.x += __shfl_down_sync(0xffffffffu, acc.x, off);
        acc.y += __shfl_down_sync(0xffffffffu, acc.y, off);
        acc.z += __shfl_down_sync(0xffffffffu, acc.z, off);
        acc.w += __shfl_down_sync(0xffffffffu, acc.w, off);
    }
    // lanes 0..3 hold dims q*4..q*4+3; epilogue computed on all lanes (harmless)
    float dv = g_dinv[n];
    float4 bq = *reinterpret_cast<const float4*>(&b1[q * 4]);
    float t0 = fmaxf(fmaf(dv, acc.x, bq.x), 0.f);
    float t1 = fmaxf(fmaf(dv, acc.y, bq.y), 0.f);
    float t2 = fmaxf(fmaf(dv, acc.z, bq.z), 0.f);
    float t3 = fmaxf(fmaf(dv, acc.w, bq.w), 0.f);
    float4 w0 = *reinterpret_cast<const float4*>(&W2[q * 8]);      // j0c0 j0c1 j1c0 j1c1
    float4 w1 = *reinterpret_cast<const float4*>(&W2[q * 8 + 4]);  // j2c0 j2c1 j3c0 j3c1
    float p0 = fmaf(t0, w0.x, fmaf(t1, w0.z, fmaf(t2, w1.x, t3 * w1.z)));
    float p1 = fmaf(t0, w0.y, fmaf(t1, w0.w, fmaf(t2, w1.y, t3 * w1.w)));
    p0 += __shfl_down_sync(0xffffffffu, p0, 2);
    p1 += __shfl_down_sync(0xffffffffu, p1, 2);
    p0 += __shfl_down_sync(0xffffffffu, p0, 1);
    p1 += __shfl_down_sync(0xffffffffu, p1, 1);
    if (lane == 0)
        *reinterpret_cast<float2*>(&g_g2[n * 2]) = make_float2(p0 * dv, p1 * dv);
}

// ---- 7) layer-2 gather + fused log_softmax ----
// warp per node; 2 lanes per edge, 16 edges/iter, unrolled x2.
__global__ __launch_bounds__(256) void k_gather2(const float* __restrict__ b2,
                                                 float* __restrict__ out) {
    int n    = (blockIdx.x * blockDim.x + threadIdx.x) >> 5;
    int lane = threadIdx.x & 31;
    int c = lane & 1;

    int ptr = g_ptr[n];
    int deg = g_cnt[n];

    float acc = (lane < 2) ? g_g2[n * 2 + c] : 0.f;          // self-loop
    int i = lane >> 1;
    for (; i + 16 < deg; i += 32) {
        int s0 = g_csr_src[ptr + i];
        int s1 = g_csr_src[ptr + i + 16];
        acc += g_g2[s0 * 2 + c] + g_g2[s1 * 2 + c];
    }
    if (i < deg) {
        int s = g_csr_src[ptr + i];
        acc += g_g2[s * 2 + c];
    }
#pragma unroll
    for (int off = 16; off >= 2; off >>= 1)
        acc += __shfl_down_sync(0xffffffffu, acc, off);       // parity preserved

    float dv = g_dinv[n];
    float z = fmaf(dv, acc, __ldg(&b2[c]));                   // valid on lanes 0,1
    float z0 = __shfl_sync(0xffffffffu, z, 0);
    float z1 = __shfl_sync(0xffffffffu, z, 1);
    if (lane == 0) {
        float m = fmaxf(z0, z1);
        float lse = m + logf(expf(z0 - m) + expf(z1 - m));
        *reinterpret_cast<float2*>(&out[n * 2]) = make_float2(z0 - lse, z1 - lse);
    }
}

extern "C" void kernel_launch(void* const* d_in, const int* in_sizes, int n_in,
                              void* d_out, int out_size) {
    const float* x      = (const float*)d_in[0];
    const int*   ei     = (const int*)d_in[1];      // int32 [2, E]
    const int*   ei_src = ei;
    const int*   ei_dst = ei + N_EDGES;
    const float* W1     = (const float*)d_in[2];
    const float* b1     = (const float*)d_in[3];
    const float* W2     = (const float*)d_in[4];
    const float* b2     = (const float*)d_in[5];
    float* out = (float*)d_out;

    const int TB = 256;
    k_zero   <<<NB_SCAN, TB>>>();
    k_cnt    <<<(N_EDGES + TB - 1) / TB, TB>>>(ei_dst);
    k_scan1  <<<NB_SCAN, TB>>>();
    k_scan2  <<<1, 512>>>();
    k_scan3  <<<NB_SCAN, TB>>>();
    k_fill   <<<(N_EDGES + TB - 1) / TB, TB>>>(ei_src, ei_dst);
    k_gemm1  <<<N_NODES / 16, 256>>>(x, W1);
    k_gather1<<<N_NODES / 8, 256>>>(b1, W2);
    k_gather2<<<N_NODES / 8, 256>>>(b2, out);
}